// round 10
// baseline (speedup 1.0000x reference)
#include <cuda_runtime.h>
#include <cuda_fp16.h>
#include <stdint.h>

#define IN_F  4096
#define OUT_F 4096
#define BATCH 4096
#define KB_CNT (IN_F / 16)     // 256 k-blocks per row-block

// ---------------- scratch (static device globals; no allocation) ----------------
// Fragment-major storage: block (rb, kb) of 16 rows x 16 k is 512 bytes at
// offset ((rb * KB_CNT + kb) * 512); within it lane l owns 16B (its mma frags).
__device__ __align__(16) __half g_wh[(size_t)OUT_F * IN_F];   // 32 MB
__device__ __align__(16) __half g_xh[(size_t)BATCH * IN_F];   // 32 MB
__device__ float g_rowsum[BATCH];
__device__ int   g_wmm[2];    // weight q min, max
__device__ int   g_bmm[2];    // bias   q min, max
__device__ float g_scal[4];   // s_w, off_w, s_b, off_b

// ---------------- PTX helpers (legal at compute_103) ----------------
__device__ __forceinline__ uint32_t smem_u32(const void* p) {
    uint32_t a;
    asm("{ .reg .u64 t; cvta.to.shared.u64 t, %1; cvt.u32.u64 %0, t; }" : "=r"(a) : "l"(p));
    return a;
}

#define CP_ASYNC16(dst, src) \
    asm volatile("cp.async.cg.shared.global [%0], [%1], 16;" :: "r"(dst), "l"(src))
#define CP_COMMIT() asm volatile("cp.async.commit_group;" ::: "memory")
#define CP_WAIT(n)  asm volatile("cp.async.wait_group %0;" :: "n"(n) : "memory")

#define LDS128(r0, r1, r2, r3, addr) \
    asm volatile("ld.shared.v4.b32 {%0,%1,%2,%3}, [%4];" \
                 : "=r"(r0), "=r"(r1), "=r"(r2), "=r"(r3) : "r"(addr))

// fp16-accumulate MMA: D(f16x2 x2) += A*B
__device__ __forceinline__ void mma16816h(uint32_t& c0, uint32_t& c1,
                                          uint32_t a0, uint32_t a1, uint32_t a2, uint32_t a3,
                                          uint32_t b0, uint32_t b1) {
    asm volatile(
        "mma.sync.aligned.m16n8k16.row.col.f16.f16.f16.f16 "
        "{%0,%1}, {%2,%3,%4,%5}, {%6,%7}, {%0,%1};"
        : "+r"(c0), "+r"(c1)
        : "r"(a0), "r"(a1), "r"(a2), "r"(a3), "r"(b0), "r"(b1));
}

// ---------------- prepass kernels ----------------
__global__ void k_init() {
    g_wmm[0] = 0x7fffffff; g_wmm[1] = (int)0x80000000;
    g_bmm[0] = 0x7fffffff; g_bmm[1] = (int)0x80000000;
}

// int32 weights -> fp16 fragment-major blocks + global min/max. One warp per block.
__global__ void k_wconv(const int* __restrict__ wq) {
    int gw = (blockIdx.x * blockDim.x + threadIdx.x) >> 5;
    int l  = threadIdx.x & 31;
    int rb = gw >> 8;
    int kb = gw & 255;
    int r = l >> 2;
    int c = (l & 3) * 2;
    const int* base = wq + (size_t)(rb * 16 + r) * IN_F + kb * 16 + c;
    int2 v0 = *(const int2*)(base);
    int2 v1 = *(const int2*)(base + 8 * IN_F);
    int2 v2 = *(const int2*)(base + 8);
    int2 v3 = *(const int2*)(base + 8 * IN_F + 8);
    __half2 h0 = __floats2half2_rn((float)v0.x, (float)v0.y);
    __half2 h1 = __floats2half2_rn((float)v1.x, (float)v1.y);
    __half2 h2 = __floats2half2_rn((float)v2.x, (float)v2.y);
    __half2 h3 = __floats2half2_rn((float)v3.x, (float)v3.y);
    uint4 o = make_uint4(*(uint32_t*)&h0, *(uint32_t*)&h1, *(uint32_t*)&h2, *(uint32_t*)&h3);
    *(uint4*)((char*)g_wh + (size_t)gw * 512 + l * 16) = o;

    int mn = min(min(v0.x, v0.y), min(v1.x, v1.y));
    mn = min(mn, min(min(v2.x, v2.y), min(v3.x, v3.y)));
    int mx = max(max(v0.x, v0.y), max(v1.x, v1.y));
    mx = max(mx, max(max(v2.x, v2.y), max(v3.x, v3.y)));
    #pragma unroll
    for (int o2 = 16; o2 > 0; o2 >>= 1) {
        mn = min(mn, __shfl_xor_sync(0xffffffffu, mn, o2));
        mx = max(mx, __shfl_xor_sync(0xffffffffu, mx, o2));
    }
    if (l == 0) {
        atomicMin(&g_wmm[0], mn);
        atomicMax(&g_wmm[1], mx);
    }
}

// x fp32 -> fp16 fragment-major blocks. One warp per block.
__global__ void k_xcvt(const float* __restrict__ x) {
    int gw = (blockIdx.x * blockDim.x + threadIdx.x) >> 5;
    int l  = threadIdx.x & 31;
    int rb = gw >> 8;
    int kb = gw & 255;
    int r = l >> 2;
    int c = (l & 3) * 2;
    const float* base = x + (size_t)(rb * 16 + r) * IN_F + kb * 16 + c;
    float2 v0 = *(const float2*)(base);
    float2 v1 = *(const float2*)(base + 8 * IN_F);
    float2 v2 = *(const float2*)(base + 8);
    float2 v3 = *(const float2*)(base + 8 * IN_F + 8);
    __half2 h0 = __floats2half2_rn(v0.x, v0.y);
    __half2 h1 = __floats2half2_rn(v1.x, v1.y);
    __half2 h2 = __floats2half2_rn(v2.x, v2.y);
    __half2 h3 = __floats2half2_rn(v3.x, v3.y);
    uint4 o = make_uint4(*(uint32_t*)&h0, *(uint32_t*)&h1, *(uint32_t*)&h2, *(uint32_t*)&h3);
    *(uint4*)((char*)g_xh + (size_t)gw * 512 + l * 16) = o;
}

// per-row sums of x
__global__ void k_rowsum(const float* __restrict__ x) {
    __shared__ float red[8];
    int row = blockIdx.x;
    int t = threadIdx.x;
    const float4* xr = (const float4*)(x + (size_t)row * IN_F);
    float s = 0.f;
    #pragma unroll
    for (int j = 0; j < 4; j++) {
        float4 v = xr[t * 4 + j];
        s += v.x + v.y + v.z + v.w;
    }
    #pragma unroll
    for (int o = 16; o > 0; o >>= 1) s += __shfl_xor_sync(0xffffffffu, s, o);
    if ((t & 31) == 0) red[t >> 5] = s;
    __syncthreads();
    if (t == 0) {
        float tot = 0.f;
        #pragma unroll
        for (int i = 0; i < 8; i++) tot += red[i];
        g_rowsum[row] = tot;
    }
}

__global__ void k_bias_mm(const int* __restrict__ bq) {
    int t = threadIdx.x;
    int mn = 0x7fffffff, mx = (int)0x80000000;
    for (int i = t; i < OUT_F; i += 256) {
        int v = bq[i];
        mn = min(mn, v); mx = max(mx, v);
    }
    #pragma unroll
    for (int o = 16; o > 0; o >>= 1) {
        mn = min(mn, __shfl_xor_sync(0xffffffffu, mn, o));
        mx = max(mx, __shfl_xor_sync(0xffffffffu, mx, o));
    }
    if ((t & 31) == 0) {
        atomicMin(&g_bmm[0], mn);
        atomicMax(&g_bmm[1], mx);
    }
}

__global__ void k_scal(const float* wmin, const float* wmax, const float* bmin, const float* bmax) {
    float s_w = (*wmax - *wmin) / (float)(g_wmm[1] - g_wmm[0]);
    g_scal[0] = s_w;
    g_scal[1] = *wmin - s_w * (float)g_wmm[0];
    float s_b = (*bmax - *bmin) / (float)(g_bmm[1] - g_bmm[0]);
    g_scal[2] = s_b;
    g_scal[3] = *bmin - s_b * (float)g_bmm[0];
}

// ---------------- GEMM ----------------
// CTA tile: 128 (M) x 128 (N), BK=64, 16 warps (4x4 of 32x32), 3-stage cp.async,
// fragment-major SMEM, LDS.128 fragment loads, fp16 accumulate within a stage,
// fp32 promotion per stage (K-chunk = 64).
#define BM      128
#define BN      128
#define BK      64
#define NSTAGE  3
#define NSTEPS  (IN_F / BK)          // 64
#define A_BYTES (8 * 4 * 512)        // 16384
#define B_BYTES (8 * 4 * 512)        // 16384
#define STG_B   (A_BYTES + B_BYTES)  // 32768
#define OFF_B   A_BYTES
#define SM_TOTAL (NSTAGE * STG_B)    // 98304
#define NTHR    512

__device__ __forceinline__ void issue_stage(char* smem, int stage, int tid,
                                            const char* abase, const char* bbase, int s) {
    uint32_t ubase = smem_u32(smem + stage * STG_B);
    // 1024 16B chunks each for A and B; 512 threads x 2 chunks each.
    #pragma unroll
    for (int j = 0; j < 2; j++) {
        int ch = j * 512 + tid;                  // 0..1023
        int mb   = ch >> 7;                      // local 16-row block 0..7
        int kb   = (ch >> 5) & 3;                // local k-block 0..3
        int lane = ch & 31;
        size_t goff = ((size_t)mb * KB_CNT + (size_t)(s * 4 + kb)) * 512 + lane * 16;
        CP_ASYNC16(ubase + ch * 16,         abase + goff);
        CP_ASYNC16(ubase + OFF_B + ch * 16, bbase + goff);
    }
}

__global__ void __launch_bounds__(NTHR, 1) k_gemm(const int* __restrict__ bias_q,
                                                  float* __restrict__ out) {
    extern __shared__ char smem[];
    int tid = threadIdx.x;
    int wid = tid >> 5, lid = tid & 31;
    int n0 = blockIdx.x * BN;
    int m0 = blockIdx.y * BM;
    int wm = (wid >> 2) * 32;        // warp m offset (4 slots of 32)
    int wn = (wid & 3) * 32;         // warp n offset (4 slots of 32)

    const char* abase = (const char*)g_xh + (size_t)(m0 / 16) * KB_CNT * 512;
    const char* bbase = (const char*)g_wh + (size_t)(n0 / 16) * KB_CNT * 512;

    float facc[2][4][4];
    uint32_t hacc[2][4][2];
    #pragma unroll
    for (int i = 0; i < 2; i++)
        #pragma unroll
        for (int j = 0; j < 4; j++) {
            hacc[i][j][0] = 0u; hacc[i][j][1] = 0u;
            #pragma unroll
            for (int q = 0; q < 4; q++) facc[i][j][q] = 0.f;
        }

    uint32_t sbase = smem_u32(smem);
    uint32_t lane16 = lid * 16;
    uint32_t aBlk[2], bBlk[2];
    #pragma unroll
    for (int f = 0; f < 2; f++) {
        aBlk[f] = ((wm >> 4) + f) * 4 * 512 + lane16;
        bBlk[f] = OFF_B + ((wn >> 4) + f) * 4 * 512 + lane16;
    }

    issue_stage(smem, 0, tid, abase, bbase, 0);
    CP_COMMIT();
    issue_stage(smem, 1, tid, abase, bbase, 1);
    CP_COMMIT();

    uint32_t aC[2][4], bC[2][4], aN[2][4], bN[2][4];

    for (int s = 0; s < NSTEPS; s++) {
        CP_WAIT(1);
        __syncthreads();
        if (s + 2 < NSTEPS)
            issue_stage(smem, (s + 2) % NSTAGE, tid, abase, bbase, s + 2);
        CP_COMMIT();   // unconditional: keeps group arithmetic valid at the tail
        uint32_t stg = sbase + (s % NSTAGE) * STG_B;

        // prime kb=0 fragments
        #pragma unroll
        for (int f = 0; f < 2; f++) {
            LDS128(aC[f][0], aC[f][1], aC[f][2], aC[f][3], stg + aBlk[f]);
            LDS128(bC[f][0], bC[f][1], bC[f][2], bC[f][3], stg + bBlk[f]);
        }
        #pragma unroll
        for (int kb = 0; kb < 4; kb++) {
            if (kb < 3) {
                uint32_t koff = (kb + 1) * 512;
                #pragma unroll
                for (int f = 0; f < 2; f++) {
                    LDS128(aN[f][0], aN[f][1], aN[f][2], aN[f][3], stg + aBlk[f] + koff);
                    LDS128(bN[f][0], bN[f][1], bN[f][2], bN[f][3], stg + bBlk[f] + koff);
                }
            }
            #pragma unroll
            for (int mf = 0; mf < 2; mf++)
                #pragma unroll
                for (int g = 0; g < 2; g++) {
                    // B block g supplies n8 frags 2g (lo: q0,q2) and 2g+1 (hi: q1,q3)
                    mma16816h(hacc[mf][2*g][0], hacc[mf][2*g][1],
                              aC[mf][0], aC[mf][1], aC[mf][2], aC[mf][3],
                              bC[g][0], bC[g][2]);
                    mma16816h(hacc[mf][2*g+1][0], hacc[mf][2*g+1][1],
                              aC[mf][0], aC[mf][1], aC[mf][2], aC[mf][3],
                              bC[g][1], bC[g][3]);
                }
            if (kb < 3) {
                #pragma unroll
                for (int f = 0; f < 2; f++)
                    #pragma unroll
                    for (int q = 0; q < 4; q++) {
                        aC[f][q] = aN[f][q];
                        bC[f][q] = bN[f][q];
                    }
            }
        }
        // promote fp16 chunk accumulators (K-chunk = 64) into fp32 and reset
        #pragma unroll
        for (int mf = 0; mf < 2; mf++)
            #pragma unroll
            for (int nf = 0; nf < 4; nf++) {
                float2 lo = __half22float2(*(__half2*)&hacc[mf][nf][0]);
                float2 hi = __half22float2(*(__half2*)&hacc[mf][nf][1]);
                facc[mf][nf][0] += lo.x;
                facc[mf][nf][1] += lo.y;
                facc[mf][nf][2] += hi.x;
                facc[mf][nf][3] += hi.y;
                hacc[mf][nf][0] = 0u;
                hacc[mf][nf][1] = 0u;
            }
        __syncthreads();
    }

    // ---------------- epilogue: y = s_w*D + off_w*rowsum + bias_deq ----------------
    float s_w = g_scal[0], off_w = g_scal[1];
    float s_b = g_scal[2], off_b = g_scal[3];
    float rs0[2], rs1[2];
    #pragma unroll
    for (int mf = 0; mf < 2; mf++) {
        int r = m0 + wm + mf * 16 + (lid >> 2);
        rs0[mf] = off_w * g_rowsum[r];
        rs1[mf] = off_w * g_rowsum[r + 8];
    }
    float bv[4][2];
    #pragma unroll
    for (int nf = 0; nf < 4; nf++) {
        int c = n0 + wn + nf * 8 + (lid & 3) * 2;
        bv[nf][0] = fmaf(s_b, (float)bias_q[c], off_b);
        bv[nf][1] = fmaf(s_b, (float)bias_q[c + 1], off_b);
    }
    #pragma unroll
    for (int mf = 0; mf < 2; mf++) {
        int r0 = m0 + wm + mf * 16 + (lid >> 2);
        #pragma unroll
        for (int nf = 0; nf < 4; nf++) {
            int c = n0 + wn + nf * 8 + (lid & 3) * 2;
            float2 v0, v1;
            v0.x = fmaf(s_w, facc[mf][nf][0], rs0[mf] + bv[nf][0]);
            v0.y = fmaf(s_w, facc[mf][nf][1], rs0[mf] + bv[nf][1]);
            v1.x = fmaf(s_w, facc[mf][nf][2], rs1[mf] + bv[nf][0]);
            v1.y = fmaf(s_w, facc[mf][nf][3], rs1[mf] + bv[nf][1]);
            *(float2*)(out + (size_t)r0 * OUT_F + c)       = v0;
            *(float2*)(out + (size_t)(r0 + 8) * OUT_F + c) = v1;
        }
    }
}

// ---------------- launch ----------------
extern "C" void kernel_launch(void* const* d_in, const int* in_sizes, int n_in,
                              void* d_out, int out_size) {
    const float* x    = (const float*)d_in[0];
    const int*   wq   = (const int*)d_in[1];
    const int*   bq   = (const int*)d_in[2];
    const float* wmin = (const float*)d_in[3];
    const float* wmax = (const float*)d_in[4];
    const float* bmin = (const float*)d_in[5];
    const float* bmax = (const float*)d_in[6];
    float* out = (float*)d_out;

    k_init<<<1, 1>>>();
    k_wconv<<<(256 * 256) / 8, 256>>>(wq);
    k_xcvt<<<(256 * 256) / 8, 256>>>(x);
    k_rowsum<<<BATCH, 256>>>(x);
    k_bias_mm<<<1, 256>>>(bq);
    k_scal<<<1, 1>>>(wmin, wmax, bmin, bmax);

    cudaFuncSetAttribute(k_gemm, cudaFuncAttributeMaxDynamicSharedMemorySize, SM_TOTAL);
    k_gemm<<<dim3(OUT_F / BN, BATCH / BM), NTHR, SM_TOTAL>>>(bq, out);
}

// round 11
// speedup vs baseline: 1.1709x; 1.1709x over previous
#include <cuda_runtime.h>
#include <cuda_fp16.h>
#include <stdint.h>

#define IN_F  4096
#define OUT_F 4096
#define BATCH 4096
#define KB_CNT (IN_F / 16)     // 256 k-blocks per row-block

// ---------------- scratch (static device globals; no allocation) ----------------
// Fragment-major storage: block (rb, kb) of 16 rows x 16 k is 512 bytes at
// offset ((rb * KB_CNT + kb) * 512); within it lane l owns 16B (its mma frags).
__device__ __align__(16) __half g_wh[(size_t)OUT_F * IN_F];   // 32 MB
__device__ __align__(16) __half g_xh[(size_t)BATCH * IN_F];   // 32 MB
__device__ float g_rowsum[BATCH];
__device__ int   g_wmm[2];    // weight q min, max
__device__ int   g_bmm[2];    // bias   q min, max
__device__ float g_scal[4];   // s_w, off_w, s_b, off_b

// ---------------- PTX helpers (legal at compute_103) ----------------
__device__ __forceinline__ uint32_t smem_u32(const void* p) {
    uint32_t a;
    asm("{ .reg .u64 t; cvta.to.shared.u64 t, %1; cvt.u32.u64 %0, t; }" : "=r"(a) : "l"(p));
    return a;
}

#define CP_ASYNC16(dst, src) \
    asm volatile("cp.async.cg.shared.global [%0], [%1], 16;" :: "r"(dst), "l"(src))
#define CP_COMMIT() asm volatile("cp.async.commit_group;" ::: "memory")
#define CP_WAIT(n)  asm volatile("cp.async.wait_group %0;" :: "n"(n) : "memory")

#define LDS128(r0, r1, r2, r3, addr) \
    asm volatile("ld.shared.v4.b32 {%0,%1,%2,%3}, [%4];" \
                 : "=r"(r0), "=r"(r1), "=r"(r2), "=r"(r3) : "r"(addr))

__device__ __forceinline__ void mma16816(float& c0, float& c1, float& c2, float& c3,
                                         uint32_t a0, uint32_t a1, uint32_t a2, uint32_t a3,
                                         uint32_t b0, uint32_t b1) {
    asm volatile(
        "mma.sync.aligned.m16n8k16.row.col.f32.f16.f16.f32 "
        "{%0,%1,%2,%3}, {%4,%5,%6,%7}, {%8,%9}, {%0,%1,%2,%3};"
        : "+f"(c0), "+f"(c1), "+f"(c2), "+f"(c3)
        : "r"(a0), "r"(a1), "r"(a2), "r"(a3), "r"(b0), "r"(b1));
}

// ---------------- prepass kernels ----------------
__global__ void k_init() {
    int i = blockIdx.x * blockDim.x + threadIdx.x;
    if (i == 0) {
        g_wmm[0] = 0x7fffffff; g_wmm[1] = (int)0x80000000;
        g_bmm[0] = 0x7fffffff; g_bmm[1] = (int)0x80000000;
    }
    if (i < BATCH) g_rowsum[i] = 0.f;
}

// int32 weights -> fp16 fragment-major blocks + global min/max. One warp per block.
__global__ void k_wconv(const int* __restrict__ wq) {
    int gw = (blockIdx.x * blockDim.x + threadIdx.x) >> 5;
    int l  = threadIdx.x & 31;
    int rb = gw >> 8;
    int kb = gw & 255;
    int r = l >> 2;
    int c = (l & 3) * 2;
    const int* base = wq + (size_t)(rb * 16 + r) * IN_F + kb * 16 + c;
    int2 v0 = *(const int2*)(base);
    int2 v1 = *(const int2*)(base + 8 * IN_F);
    int2 v2 = *(const int2*)(base + 8);
    int2 v3 = *(const int2*)(base + 8 * IN_F + 8);
    __half2 h0 = __floats2half2_rn((float)v0.x, (float)v0.y);
    __half2 h1 = __floats2half2_rn((float)v1.x, (float)v1.y);
    __half2 h2 = __floats2half2_rn((float)v2.x, (float)v2.y);
    __half2 h3 = __floats2half2_rn((float)v3.x, (float)v3.y);
    uint4 o = make_uint4(*(uint32_t*)&h0, *(uint32_t*)&h1, *(uint32_t*)&h2, *(uint32_t*)&h3);
    *(uint4*)((char*)g_wh + (size_t)gw * 512 + l * 16) = o;

    int mn = min(min(v0.x, v0.y), min(v1.x, v1.y));
    mn = min(mn, min(min(v2.x, v2.y), min(v3.x, v3.y)));
    int mx = max(max(v0.x, v0.y), max(v1.x, v1.y));
    mx = max(mx, max(max(v2.x, v2.y), max(v3.x, v3.y)));
    #pragma unroll
    for (int o2 = 16; o2 > 0; o2 >>= 1) {
        mn = min(mn, __shfl_xor_sync(0xffffffffu, mn, o2));
        mx = max(mx, __shfl_xor_sync(0xffffffffu, mx, o2));
    }
    if (l == 0) {
        atomicMin(&g_wmm[0], mn);
        atomicMax(&g_wmm[1], mx);
    }
}

// x fp32 -> fp16 fragment-major blocks, fused per-row-sum accumulation.
__global__ void k_xcvt(const float* __restrict__ x) {
    int gw = (blockIdx.x * blockDim.x + threadIdx.x) >> 5;
    int l  = threadIdx.x & 31;
    int rb = gw >> 8;
    int kb = gw & 255;
    int r = l >> 2;
    int c = (l & 3) * 2;
    const float* base = x + (size_t)(rb * 16 + r) * IN_F + kb * 16 + c;
    float2 v0 = *(const float2*)(base);
    float2 v1 = *(const float2*)(base + 8 * IN_F);
    float2 v2 = *(const float2*)(base + 8);
    float2 v3 = *(const float2*)(base + 8 * IN_F + 8);
    __half2 h0 = __floats2half2_rn(v0.x, v0.y);
    __half2 h1 = __floats2half2_rn(v1.x, v1.y);
    __half2 h2 = __floats2half2_rn(v2.x, v2.y);
    __half2 h3 = __floats2half2_rn(v3.x, v3.y);
    uint4 o = make_uint4(*(uint32_t*)&h0, *(uint32_t*)&h1, *(uint32_t*)&h2, *(uint32_t*)&h3);
    *(uint4*)((char*)g_xh + (size_t)gw * 512 + l * 16) = o;

    // fused row sums: lane l holds 4 values of row r and 4 of row r+8 (16 k-cols
    // split across the 4 lanes sharing r). Reduce over those 4 lanes, then atomic.
    float slo = v0.x + v0.y + v2.x + v2.y;     // row rb*16 + r
    float shi = v1.x + v1.y + v3.x + v3.y;     // row rb*16 + r + 8
    slo += __shfl_xor_sync(0xffffffffu, slo, 1);
    slo += __shfl_xor_sync(0xffffffffu, slo, 2);
    shi += __shfl_xor_sync(0xffffffffu, shi, 1);
    shi += __shfl_xor_sync(0xffffffffu, shi, 2);
    if ((l & 3) == 0) {
        atomicAdd(&g_rowsum[rb * 16 + r], slo);
        atomicAdd(&g_rowsum[rb * 16 + r + 8], shi);
    }
}

__global__ void k_bias_mm(const int* __restrict__ bq) {
    int t = threadIdx.x;
    int mn = 0x7fffffff, mx = (int)0x80000000;
    for (int i = t; i < OUT_F; i += 256) {
        int v = bq[i];
        mn = min(mn, v); mx = max(mx, v);
    }
    #pragma unroll
    for (int o = 16; o > 0; o >>= 1) {
        mn = min(mn, __shfl_xor_sync(0xffffffffu, mn, o));
        mx = max(mx, __shfl_xor_sync(0xffffffffu, mx, o));
    }
    if ((t & 31) == 0) {
        atomicMin(&g_bmm[0], mn);
        atomicMax(&g_bmm[1], mx);
    }
}

__global__ void k_scal(const float* wmin, const float* wmax, const float* bmin, const float* bmax) {
    float s_w = (*wmax - *wmin) / (float)(g_wmm[1] - g_wmm[0]);
    g_scal[0] = s_w;
    g_scal[1] = *wmin - s_w * (float)g_wmm[0];
    float s_b = (*bmax - *bmin) / (float)(g_bmm[1] - g_bmm[0]);
    g_scal[2] = s_b;
    g_scal[3] = *bmin - s_b * (float)g_bmm[0];
}

// ---------------- GEMM ----------------
// CTA tile: 64 (M) x 128 (N), BK=64, 4 warps (2x2 of 32x64), 4-stage cp.async,
// fragment-major SMEM, LDS.128 fragment loads, register double-buffering,
// 2 CTAs/SM (96 KB smem each), 2048 tiles -> 6.92 waves (tail ~1%).
#define BM      64
#define BN      128
#define BK      64
#define NSTAGE  4
#define NSTEPS  (IN_F / BK)          // 64
#define A_BYTES (4 * 4 * 512)        // 4 m-blocks x 4 k-blocks x 512B = 8192
#define B_BYTES (8 * 4 * 512)        // 16384
#define STG_B   (A_BYTES + B_BYTES)  // 24576
#define OFF_B   A_BYTES
#define SM_TOTAL (NSTAGE * STG_B)    // 98304
#define NTHR    128

__device__ __forceinline__ void issue_stage(char* smem, int stage, int tid,
                                            const char* abase, const char* bbase, int s) {
    uint32_t ubase = smem_u32(smem + stage * STG_B);
    // A: 512 16B chunks; 128 threads x 4.
    #pragma unroll
    for (int j = 0; j < 4; j++) {
        int ch = j * 128 + tid;                  // 0..511
        int mb   = ch >> 7;                      // 0..3
        int kb   = (ch >> 5) & 3;
        int lane = ch & 31;
        size_t goff = ((size_t)mb * KB_CNT + (size_t)(s * 4 + kb)) * 512 + lane * 16;
        CP_ASYNC16(ubase + ch * 16, abase + goff);
    }
    // B: 1024 16B chunks; 128 threads x 8.
    #pragma unroll
    for (int j = 0; j < 8; j++) {
        int ch = j * 128 + tid;                  // 0..1023
        int mb   = ch >> 7;                      // 0..7
        int kb   = (ch >> 5) & 3;
        int lane = ch & 31;
        size_t goff = ((size_t)mb * KB_CNT + (size_t)(s * 4 + kb)) * 512 + lane * 16;
        CP_ASYNC16(ubase + OFF_B + ch * 16, bbase + goff);
    }
}

__global__ void __launch_bounds__(NTHR, 2) k_gemm(const int* __restrict__ bias_q,
                                                  float* __restrict__ out) {
    extern __shared__ char smem[];
    int tid = threadIdx.x;
    int wid = tid >> 5, lid = tid & 31;
    int n0 = blockIdx.x * BN;
    int m0 = blockIdx.y * BM;
    int wm = (wid >> 1) * 32;        // warp m offset (2 slots of 32)
    int wn = (wid & 1) * 64;         // warp n offset (2 slots of 64)

    const char* abase = (const char*)g_xh + (size_t)(m0 / 16) * KB_CNT * 512;
    const char* bbase = (const char*)g_wh + (size_t)(n0 / 16) * KB_CNT * 512;

    float acc[2][8][4];
    #pragma unroll
    for (int i = 0; i < 2; i++)
        #pragma unroll
        for (int j = 0; j < 8; j++)
            #pragma unroll
            for (int q = 0; q < 4; q++) acc[i][j][q] = 0.f;

    uint32_t sbase = smem_u32(smem);
    uint32_t lane16 = lid * 16;
    uint32_t aBlk[2], bBlk[4];
    #pragma unroll
    for (int f = 0; f < 2; f++)
        aBlk[f] = ((wm >> 4) + f) * 4 * 512 + lane16;
    #pragma unroll
    for (int g = 0; g < 4; g++)
        bBlk[g] = OFF_B + ((wn >> 4) + g) * 4 * 512 + lane16;

    issue_stage(smem, 0, tid, abase, bbase, 0);
    CP_COMMIT();
    issue_stage(smem, 1, tid, abase, bbase, 1);
    CP_COMMIT();
    issue_stage(smem, 2, tid, abase, bbase, 2);
    CP_COMMIT();

    uint32_t aC[2][4], bC[4][4], aN[2][4], bN[4][4];

    for (int s = 0; s < NSTEPS; s++) {
        CP_WAIT(2);
        __syncthreads();
        if (s + 3 < NSTEPS)
            issue_stage(smem, (s + 3) % NSTAGE, tid, abase, bbase, s + 3);
        CP_COMMIT();   // unconditional: keeps group arithmetic valid at the tail
        uint32_t stg = sbase + (s % NSTAGE) * STG_B;

        // prime kb=0 fragments
        #pragma unroll
        for (int f = 0; f < 2; f++)
            LDS128(aC[f][0], aC[f][1], aC[f][2], aC[f][3], stg + aBlk[f]);
        #pragma unroll
        for (int g = 0; g < 4; g++)
            LDS128(bC[g][0], bC[g][1], bC[g][2], bC[g][3], stg + bBlk[g]);

        #pragma unroll
        for (int kb = 0; kb < 4; kb++) {
            if (kb < 3) {
                uint32_t koff = (kb + 1) * 512;
                #pragma unroll
                for (int f = 0; f < 2; f++)
                    LDS128(aN[f][0], aN[f][1], aN[f][2], aN[f][3], stg + aBlk[f] + koff);
                #pragma unroll
                for (int g = 0; g < 4; g++)
                    LDS128(bN[g][0], bN[g][1], bN[g][2], bN[g][3], stg + bBlk[g] + koff);
            }
            #pragma unroll
            for (int mf = 0; mf < 2; mf++)
                #pragma unroll
                for (int g = 0; g < 4; g++) {
                    // B block g supplies n8 frags 2g (lo: q0,q2) and 2g+1 (hi: q1,q3)
                    mma16816(acc[mf][2*g][0], acc[mf][2*g][1], acc[mf][2*g][2], acc[mf][2*g][3],
                             aC[mf][0], aC[mf][1], aC[mf][2], aC[mf][3],
                             bC[g][0], bC[g][2]);
                    mma16816(acc[mf][2*g+1][0], acc[mf][2*g+1][1], acc[mf][2*g+1][2], acc[mf][2*g+1][3],
                             aC[mf][0], aC[mf][1], aC[mf][2], aC[mf][3],
                             bC[g][1], bC[g][3]);
                }
            if (kb < 3) {
                #pragma unroll
                for (int f = 0; f < 2; f++)
                    #pragma unroll
                    for (int q = 0; q < 4; q++) aC[f][q] = aN[f][q];
                #pragma unroll
                for (int g = 0; g < 4; g++)
                    #pragma unroll
                    for (int q = 0; q < 4; q++) bC[g][q] = bN[g][q];
            }
        }
        __syncthreads();
    }

    // ---------------- epilogue: y = s_w*D + off_w*rowsum + bias_deq ----------------
    float s_w = g_scal[0], off_w = g_scal[1];
    float s_b = g_scal[2], off_b = g_scal[3];
    float rs0[2], rs1[2];
    #pragma unroll
    for (int mf = 0; mf < 2; mf++) {
        int r = m0 + wm + mf * 16 + (lid >> 2);
        rs0[mf] = off_w * g_rowsum[r];
        rs1[mf] = off_w * g_rowsum[r + 8];
    }
    float bv[8][2];
    #pragma unroll
    for (int nf = 0; nf < 8; nf++) {
        int c = n0 + wn + nf * 8 + (lid & 3) * 2;
        bv[nf][0] = fmaf(s_b, (float)bias_q[c], off_b);
        bv[nf][1] = fmaf(s_b, (float)bias_q[c + 1], off_b);
    }
    #pragma unroll
    for (int mf = 0; mf < 2; mf++) {
        int r0 = m0 + wm + mf * 16 + (lid >> 2);
        #pragma unroll
        for (int nf = 0; nf < 8; nf++) {
            int c = n0 + wn + nf * 8 + (lid & 3) * 2;
            float2 v0, v1;
            v0.x = fmaf(s_w, acc[mf][nf][0], rs0[mf] + bv[nf][0]);
            v0.y = fmaf(s_w, acc[mf][nf][1], rs0[mf] + bv[nf][1]);
            v1.x = fmaf(s_w, acc[mf][nf][2], rs1[mf] + bv[nf][0]);
            v1.y = fmaf(s_w, acc[mf][nf][3], rs1[mf] + bv[nf][1]);
            *(float2*)(out + (size_t)r0 * OUT_F + c)       = v0;
            *(float2*)(out + (size_t)(r0 + 8) * OUT_F + c) = v1;
        }
    }
}

// ---------------- launch ----------------
extern "C" void kernel_launch(void* const* d_in, const int* in_sizes, int n_in,
                              void* d_out, int out_size) {
    const float* x    = (const float*)d_in[0];
    const int*   wq   = (const int*)d_in[1];
    const int*   bq   = (const int*)d_in[2];
    const float* wmin = (const float*)d_in[3];
    const float* wmax = (const float*)d_in[4];
    const float* bmin = (const float*)d_in[5];
    const float* bmax = (const float*)d_in[6];
    float* out = (float*)d_out;

    k_init<<<(BATCH + 255) / 256, 256>>>();
    k_wconv<<<(256 * 256) / 8, 256>>>(wq);
    k_xcvt<<<(256 * 256) / 8, 256>>>(x);
    k_bias_mm<<<1, 256>>>(bq);
    k_scal<<<1, 1>>>(wmin, wmax, bmin, bmax);

    cudaFuncSetAttribute(k_gemm, cudaFuncAttributeMaxDynamicSharedMemorySize, SM_TOTAL);
    k_gemm<<<dim3(OUT_F / BN, BATCH / BM), NTHR, SM_TOTAL>>>(bq, out);
}

// round 12
// speedup vs baseline: 1.2278x; 1.0486x over previous
#include <cuda_runtime.h>
#include <cuda_fp16.h>
#include <stdint.h>

#define IN_F  4096
#define OUT_F 4096
#define BATCH 4096
#define KB_CNT (IN_F / 16)     // 256 k-blocks per row-block

// ---------------- scratch (static device globals; no allocation) ----------------
// Fragment-major storage: block (rb, kb) of 16 rows x 16 k is 512 bytes at
// offset ((rb * KB_CNT + kb) * 512); within it lane l owns 16B (its mma frags).
__device__ __align__(16) __half g_wh[(size_t)OUT_F * IN_F];   // 32 MB
__device__ __align__(16) __half g_xh[(size_t)BATCH * IN_F];   // 32 MB
__device__ float g_rowsum[BATCH];
__device__ int   g_wmm[2];    // weight q min, max
__device__ int   g_bmm[2];    // bias   q min, max

// ---------------- PTX helpers (legal at compute_103) ----------------
__device__ __forceinline__ uint32_t smem_u32(const void* p) {
    uint32_t a;
    asm("{ .reg .u64 t; cvta.to.shared.u64 t, %1; cvt.u32.u64 %0, t; }" : "=r"(a) : "l"(p));
    return a;
}

#define CP_ASYNC16(dst, src) \
    asm volatile("cp.async.cg.shared.global [%0], [%1], 16;" :: "r"(dst), "l"(src))
#define CP_COMMIT() asm volatile("cp.async.commit_group;" ::: "memory")
#define CP_WAIT(n)  asm volatile("cp.async.wait_group %0;" :: "n"(n) : "memory")

#define LDS128(r0, r1, r2, r3, addr) \
    asm volatile("ld.shared.v4.b32 {%0,%1,%2,%3}, [%4];" \
                 : "=r"(r0), "=r"(r1), "=r"(r2), "=r"(r3) : "r"(addr))

__device__ __forceinline__ void mma16816(float& c0, float& c1, float& c2, float& c3,
                                         uint32_t a0, uint32_t a1, uint32_t a2, uint32_t a3,
                                         uint32_t b0, uint32_t b1) {
    asm volatile(
        "mma.sync.aligned.m16n8k16.row.col.f32.f16.f16.f32 "
        "{%0,%1,%2,%3}, {%4,%5,%6,%7}, {%8,%9}, {%0,%1,%2,%3};"
        : "+f"(c0), "+f"(c1), "+f"(c2), "+f"(c3)
        : "r"(a0), "r"(a1), "r"(a2), "r"(a3), "r"(b0), "r"(b1));
}

// ---------------- prepass kernels ----------------
__global__ void k_init() {
    int i = blockIdx.x * blockDim.x + threadIdx.x;
    if (i == 0) {
        g_wmm[0] = 0x7fffffff; g_wmm[1] = (int)0x80000000;
        g_bmm[0] = 0x7fffffff; g_bmm[1] = (int)0x80000000;
    }
    if (i < BATCH) g_rowsum[i] = 0.f;
}

// int32 weights -> fp16 fragment-major blocks + global min/max. One warp per block.
__global__ void k_wconv(const int* __restrict__ wq) {
    int gw = (blockIdx.x * blockDim.x + threadIdx.x) >> 5;
    int l  = threadIdx.x & 31;
    int rb = gw >> 8;
    int kb = gw & 255;
    int r = l >> 2;
    int c = (l & 3) * 2;
    const int* base = wq + (size_t)(rb * 16 + r) * IN_F + kb * 16 + c;
    int2 v0 = *(const int2*)(base);
    int2 v1 = *(const int2*)(base + 8 * IN_F);
    int2 v2 = *(const int2*)(base + 8);
    int2 v3 = *(const int2*)(base + 8 * IN_F + 8);
    __half2 h0 = __floats2half2_rn((float)v0.x, (float)v0.y);
    __half2 h1 = __floats2half2_rn((float)v1.x, (float)v1.y);
    __half2 h2 = __floats2half2_rn((float)v2.x, (float)v2.y);
    __half2 h3 = __floats2half2_rn((float)v3.x, (float)v3.y);
    uint4 o = make_uint4(*(uint32_t*)&h0, *(uint32_t*)&h1, *(uint32_t*)&h2, *(uint32_t*)&h3);
    *(uint4*)((char*)g_wh + (size_t)gw * 512 + l * 16) = o;

    int mn = min(min(v0.x, v0.y), min(v1.x, v1.y));
    mn = min(mn, min(min(v2.x, v2.y), min(v3.x, v3.y)));
    int mx = max(max(v0.x, v0.y), max(v1.x, v1.y));
    mx = max(mx, max(max(v2.x, v2.y), max(v3.x, v3.y)));
    #pragma unroll
    for (int o2 = 16; o2 > 0; o2 >>= 1) {
        mn = min(mn, __shfl_xor_sync(0xffffffffu, mn, o2));
        mx = max(mx, __shfl_xor_sync(0xffffffffu, mx, o2));
    }
    if (l == 0) {
        atomicMin(&g_wmm[0], mn);
        atomicMax(&g_wmm[1], mx);
    }
}

// x fp32 -> fp16 fragment-major blocks, fused per-row-sum accumulation.
__global__ void k_xcvt(const float* __restrict__ x) {
    int gw = (blockIdx.x * blockDim.x + threadIdx.x) >> 5;
    int l  = threadIdx.x & 31;
    int rb = gw >> 8;
    int kb = gw & 255;
    int r = l >> 2;
    int c = (l & 3) * 2;
    const float* base = x + (size_t)(rb * 16 + r) * IN_F + kb * 16 + c;
    float2 v0 = *(const float2*)(base);
    float2 v1 = *(const float2*)(base + 8 * IN_F);
    float2 v2 = *(const float2*)(base + 8);
    float2 v3 = *(const float2*)(base + 8 * IN_F + 8);
    __half2 h0 = __floats2half2_rn(v0.x, v0.y);
    __half2 h1 = __floats2half2_rn(v1.x, v1.y);
    __half2 h2 = __floats2half2_rn(v2.x, v2.y);
    __half2 h3 = __floats2half2_rn(v3.x, v3.y);
    uint4 o = make_uint4(*(uint32_t*)&h0, *(uint32_t*)&h1, *(uint32_t*)&h2, *(uint32_t*)&h3);
    *(uint4*)((char*)g_xh + (size_t)gw * 512 + l * 16) = o;

    // fused row sums (reduce over the 4 lanes sharing a row, then one atomic)
    float slo = v0.x + v0.y + v2.x + v2.y;     // row rb*16 + r
    float shi = v1.x + v1.y + v3.x + v3.y;     // row rb*16 + r + 8
    slo += __shfl_xor_sync(0xffffffffu, slo, 1);
    slo += __shfl_xor_sync(0xffffffffu, slo, 2);
    shi += __shfl_xor_sync(0xffffffffu, shi, 1);
    shi += __shfl_xor_sync(0xffffffffu, shi, 2);
    if ((l & 3) == 0) {
        atomicAdd(&g_rowsum[rb * 16 + r], slo);
        atomicAdd(&g_rowsum[rb * 16 + r + 8], shi);
    }
}

// bias min/max (8 blocks to avoid single-block latency)
__global__ void k_bias_mm(const int* __restrict__ bq) {
    int i0 = blockIdx.x * 512;
    int t = threadIdx.x;
    int mn = 0x7fffffff, mx = (int)0x80000000;
    #pragma unroll
    for (int j = 0; j < 2; j++) {
        int v = bq[i0 + j * 256 + t];
        mn = min(mn, v); mx = max(mx, v);
    }
    #pragma unroll
    for (int o = 16; o > 0; o >>= 1) {
        mn = min(mn, __shfl_xor_sync(0xffffffffu, mn, o));
        mx = max(mx, __shfl_xor_sync(0xffffffffu, mx, o));
    }
    if ((t & 31) == 0) {
        atomicMin(&g_bmm[0], mn);
        atomicMax(&g_bmm[1], mx);
    }
}

// ---------------- GEMM ----------------
// CTA tile: 128 (M) x 128 (N), BK=64, 4 warps (2x2 of 64x64), 3-stage cp.async,
// fragment-major SMEM, LDS.128 fragment loads, parity ping-pong register
// buffering (no copies), 2 CTAs/SM. Scales computed inline (no k_scal launch).
#define BM      128
#define BN      128
#define BK      64
#define NSTAGE  3
#define NSTEPS  (IN_F / BK)          // 64
#define A_BYTES (8 * 4 * 512)        // 16384
#define B_BYTES (8 * 4 * 512)        // 16384
#define STG_B   (A_BYTES + B_BYTES)  // 32768
#define OFF_B   A_BYTES
#define SM_TOTAL (NSTAGE * STG_B)    // 98304
#define NTHR    128

__device__ __forceinline__ void issue_stage(char* smem, int stage, int tid,
                                            const char* abase, const char* bbase, int s) {
    uint32_t ubase = smem_u32(smem + stage * STG_B);
    #pragma unroll
    for (int j = 0; j < 8; j++) {
        int ch = j * 128 + tid;                  // 0..1023
        int mb   = ch >> 7;                      // local 16-row block 0..7
        int kb   = (ch >> 5) & 3;                // local k-block 0..3
        int lane = ch & 31;
        size_t goff = ((size_t)mb * KB_CNT + (size_t)(s * 4 + kb)) * 512 + lane * 16;
        CP_ASYNC16(ubase + ch * 16,         abase + goff);
        CP_ASYNC16(ubase + OFF_B + ch * 16, bbase + goff);
    }
}

__global__ void __launch_bounds__(NTHR, 2) k_gemm(
    const int* __restrict__ bias_q, float* __restrict__ out,
    const float* __restrict__ wmin, const float* __restrict__ wmax,
    const float* __restrict__ bmin, const float* __restrict__ bmax) {
    extern __shared__ char smem[];
    int tid = threadIdx.x;
    int wid = tid >> 5, lid = tid & 31;
    int n0 = blockIdx.x * BN;
    int m0 = blockIdx.y * BM;
    int wm = (wid >> 1) * 64;        // warp m offset (2 slots of 64)
    int wn = (wid & 1) * 64;         // warp n offset (2 slots of 64)

    // inline scale computation (constant per grid; cheap per CTA)
    float s_w = (*wmax - *wmin) / (float)(g_wmm[1] - g_wmm[0]);
    float off_w = *wmin - s_w * (float)g_wmm[0];
    float s_b = (*bmax - *bmin) / (float)(g_bmm[1] - g_bmm[0]);
    float off_b = *bmin - s_b * (float)g_bmm[0];

    const char* abase = (const char*)g_xh + (size_t)(m0 / 16) * KB_CNT * 512;
    const char* bbase = (const char*)g_wh + (size_t)(n0 / 16) * KB_CNT * 512;

    float acc[4][8][4];
    #pragma unroll
    for (int i = 0; i < 4; i++)
        #pragma unroll
        for (int j = 0; j < 8; j++)
            #pragma unroll
            for (int q = 0; q < 4; q++) acc[i][j][q] = 0.f;

    uint32_t sbase = smem_u32(smem);
    uint32_t lane16 = lid * 16;
    uint32_t aBlk[4], bBlk[4];
    #pragma unroll
    for (int f = 0; f < 4; f++) {
        aBlk[f] = ((wm >> 4) + f) * 4 * 512 + lane16;
        bBlk[f] = OFF_B + ((wn >> 4) + f) * 4 * 512 + lane16;
    }

    issue_stage(smem, 0, tid, abase, bbase, 0);
    CP_COMMIT();
    issue_stage(smem, 1, tid, abase, bbase, 1);
    CP_COMMIT();

    // parity ping-pong register buffers (no copies; kb loop fully unrolled)
    uint32_t aR[2][4][4], bR[2][4][4];

    for (int s = 0; s < NSTEPS; s++) {
        CP_WAIT(1);
        __syncthreads();
        if (s + 2 < NSTEPS)
            issue_stage(smem, (s + 2) % NSTAGE, tid, abase, bbase, s + 2);
        CP_COMMIT();   // unconditional: keeps group arithmetic valid at the tail
        uint32_t stg = sbase + (s % NSTAGE) * STG_B;

        // prime kb=0 into parity buffer 0
        #pragma unroll
        for (int f = 0; f < 4; f++) {
            LDS128(aR[0][f][0], aR[0][f][1], aR[0][f][2], aR[0][f][3], stg + aBlk[f]);
            LDS128(bR[0][f][0], bR[0][f][1], bR[0][f][2], bR[0][f][3], stg + bBlk[f]);
        }
        #pragma unroll
        for (int kb = 0; kb < 4; kb++) {
            const int cur = kb & 1, nxt = cur ^ 1;
            if (kb < 3) {
                uint32_t koff = (kb + 1) * 512;
                #pragma unroll
                for (int f = 0; f < 4; f++) {
                    LDS128(aR[nxt][f][0], aR[nxt][f][1], aR[nxt][f][2], aR[nxt][f][3],
                           stg + aBlk[f] + koff);
                    LDS128(bR[nxt][f][0], bR[nxt][f][1], bR[nxt][f][2], bR[nxt][f][3],
                           stg + bBlk[f] + koff);
                }
            }
            #pragma unroll
            for (int mf = 0; mf < 4; mf++)
                #pragma unroll
                for (int g = 0; g < 4; g++) {
                    // B block g supplies n8 frags 2g (lo: q0,q2) and 2g+1 (hi: q1,q3)
                    mma16816(acc[mf][2*g][0], acc[mf][2*g][1], acc[mf][2*g][2], acc[mf][2*g][3],
                             aR[cur][mf][0], aR[cur][mf][1], aR[cur][mf][2], aR[cur][mf][3],
                             bR[cur][g][0], bR[cur][g][2]);
                    mma16816(acc[mf][2*g+1][0], acc[mf][2*g+1][1], acc[mf][2*g+1][2], acc[mf][2*g+1][3],
                             aR[cur][mf][0], aR[cur][mf][1], aR[cur][mf][2], aR[cur][mf][3],
                             bR[cur][g][1], bR[cur][g][3]);
                }
        }
        __syncthreads();
    }

    // ---------------- epilogue: y = s_w*D + off_w*rowsum + bias_deq ----------------
    float rs0[4], rs1[4];
    #pragma unroll
    for (int mf = 0; mf < 4; mf++) {
        int r = m0 + wm + mf * 16 + (lid >> 2);
        rs0[mf] = off_w * g_rowsum[r];
        rs1[mf] = off_w * g_rowsum[r + 8];
    }
    float bv[8][2];
    #pragma unroll
    for (int nf = 0; nf < 8; nf++) {
        int c = n0 + wn + nf * 8 + (lid & 3) * 2;
        bv[nf][0] = fmaf(s_b, (float)bias_q[c], off_b);
        bv[nf][1] = fmaf(s_b, (float)bias_q[c + 1], off_b);
    }
    #pragma unroll
    for (int mf = 0; mf < 4; mf++) {
        int r0 = m0 + wm + mf * 16 + (lid >> 2);
        #pragma unroll
        for (int nf = 0; nf < 8; nf++) {
            int c = n0 + wn + nf * 8 + (lid & 3) * 2;
            float2 v0, v1;
            v0.x = fmaf(s_w, acc[mf][nf][0], rs0[mf] + bv[nf][0]);
            v0.y = fmaf(s_w, acc[mf][nf][1], rs0[mf] + bv[nf][1]);
            v1.x = fmaf(s_w, acc[mf][nf][2], rs1[mf] + bv[nf][0]);
            v1.y = fmaf(s_w, acc[mf][nf][3], rs1[mf] + bv[nf][1]);
            *(float2*)(out + (size_t)r0 * OUT_F + c)       = v0;
            *(float2*)(out + (size_t)(r0 + 8) * OUT_F + c) = v1;
        }
    }
}

// ---------------- launch ----------------
extern "C" void kernel_launch(void* const* d_in, const int* in_sizes, int n_in,
                              void* d_out, int out_size) {
    const float* x    = (const float*)d_in[0];
    const int*   wq   = (const int*)d_in[1];
    const int*   bq   = (const int*)d_in[2];
    const float* wmin = (const float*)d_in[3];
    const float* wmax = (const float*)d_in[4];
    const float* bmin = (const float*)d_in[5];
    const float* bmax = (const float*)d_in[6];
    float* out = (float*)d_out;

    k_init<<<(BATCH + 255) / 256, 256>>>();
    k_wconv<<<(256 * 256) / 8, 256>>>(wq);
    k_xcvt<<<(256 * 256) / 8, 256>>>(x);
    k_bias_mm<<<8, 256>>>(bq);

    cudaFuncSetAttribute(k_gemm, cudaFuncAttributeMaxDynamicSharedMemorySize, SM_TOTAL);
    k_gemm<<<dim3(OUT_F / BN, BATCH / BM), NTHR, SM_TOTAL>>>(bq, out, wmin, wmax, bmin, bmax);
}

// round 13
// speedup vs baseline: 1.2581x; 1.0247x over previous
#include <cuda_runtime.h>
#include <cuda_fp16.h>
#include <stdint.h>

#define IN_F  4096
#define OUT_F 4096
#define BATCH 4096
#define KB_CNT (IN_F / 16)     // 256 k-blocks per row-block

// ---------------- scratch (static device globals; no allocation) ----------------
// Fragment-major storage: block (rb, kb) of 16 rows x 16 k is 512 bytes at
// offset ((rb * KB_CNT + kb) * 512); within it lane l owns 16B (its mma frags).
__device__ __align__(16) __half g_wh[(size_t)OUT_F * IN_F];   // 32 MB
__device__ __align__(16) __half g_xh[(size_t)BATCH * IN_F];   // 32 MB
__device__ float g_rowsum[BATCH];
__device__ int   g_wmm[2];    // weight q min, max
__device__ int   g_bmm[2];    // bias   q min, max

// ---------------- PTX helpers (legal at compute_103) ----------------
__device__ __forceinline__ uint32_t smem_u32(const void* p) {
    uint32_t a;
    asm("{ .reg .u64 t; cvta.to.shared.u64 t, %1; cvt.u32.u64 %0, t; }" : "=r"(a) : "l"(p));
    return a;
}

#define CP_ASYNC16(dst, src) \
    asm volatile("cp.async.cg.shared.global [%0], [%1], 16;" :: "r"(dst), "l"(src))
#define CP_COMMIT() asm volatile("cp.async.commit_group;" ::: "memory")
#define CP_WAIT(n)  asm volatile("cp.async.wait_group %0;" :: "n"(n) : "memory")

#define LDS128(r0, r1, r2, r3, addr) \
    asm volatile("ld.shared.v4.b32 {%0,%1,%2,%3}, [%4];" \
                 : "=r"(r0), "=r"(r1), "=r"(r2), "=r"(r3) : "r"(addr))

__device__ __forceinline__ void mma16816(float& c0, float& c1, float& c2, float& c3,
                                         uint32_t a0, uint32_t a1, uint32_t a2, uint32_t a3,
                                         uint32_t b0, uint32_t b1) {
    asm volatile(
        "mma.sync.aligned.m16n8k16.row.col.f32.f16.f16.f32 "
        "{%0,%1,%2,%3}, {%4,%5,%6,%7}, {%8,%9}, {%0,%1,%2,%3};"
        : "+f"(c0), "+f"(c1), "+f"(c2), "+f"(c3)
        : "r"(a0), "r"(a1), "r"(a2), "r"(a3), "r"(b0), "r"(b1));
}

// ---------------- prepass kernels ----------------
__global__ void k_init() {
    int i = blockIdx.x * blockDim.x + threadIdx.x;
    if (i == 0) {
        g_wmm[0] = 0x7fffffff; g_wmm[1] = (int)0x80000000;
        g_bmm[0] = 0x7fffffff; g_bmm[1] = (int)0x80000000;
    }
    if (i < BATCH) g_rowsum[i] = 0.f;
}

// Fused prepass: blocks [0, 8192) convert weights, [8192, 16384) convert x,
// [16384, 16392) reduce bias min/max.
#define WCONV_BLKS 8192
#define XCVT_BLKS  8192
__global__ void k_prep(const int* __restrict__ wq, const float* __restrict__ x,
                       const int* __restrict__ bq) {
    int b = blockIdx.x;
    int tid = threadIdx.x;
    int l = tid & 31;

    if (b < WCONV_BLKS) {
        // ---- weights: int32 -> fp16 fragment-major + global min/max ----
        int gw = (b * 256 + tid) >> 5;
        int rb = gw >> 8;
        int kb = gw & 255;
        int r = l >> 2;
        int c = (l & 3) * 2;
        const int* base = wq + (size_t)(rb * 16 + r) * IN_F + kb * 16 + c;
        int2 v0 = *(const int2*)(base);
        int2 v1 = *(const int2*)(base + 8 * IN_F);
        int2 v2 = *(const int2*)(base + 8);
        int2 v3 = *(const int2*)(base + 8 * IN_F + 8);
        __half2 h0 = __floats2half2_rn((float)v0.x, (float)v0.y);
        __half2 h1 = __floats2half2_rn((float)v1.x, (float)v1.y);
        __half2 h2 = __floats2half2_rn((float)v2.x, (float)v2.y);
        __half2 h3 = __floats2half2_rn((float)v3.x, (float)v3.y);
        uint4 o = make_uint4(*(uint32_t*)&h0, *(uint32_t*)&h1, *(uint32_t*)&h2, *(uint32_t*)&h3);
        *(uint4*)((char*)g_wh + (size_t)gw * 512 + l * 16) = o;

        int mn = min(min(v0.x, v0.y), min(v1.x, v1.y));
        mn = min(mn, min(min(v2.x, v2.y), min(v3.x, v3.y)));
        int mx = max(max(v0.x, v0.y), max(v1.x, v1.y));
        mx = max(mx, max(max(v2.x, v2.y), max(v3.x, v3.y)));
        #pragma unroll
        for (int o2 = 16; o2 > 0; o2 >>= 1) {
            mn = min(mn, __shfl_xor_sync(0xffffffffu, mn, o2));
            mx = max(mx, __shfl_xor_sync(0xffffffffu, mx, o2));
        }
        if (l == 0) {
            atomicMin(&g_wmm[0], mn);
            atomicMax(&g_wmm[1], mx);
        }
    } else if (b < WCONV_BLKS + XCVT_BLKS) {
        // ---- x: fp32 -> fp16 fragment-major + fused row sums ----
        int gw = ((b - WCONV_BLKS) * 256 + tid) >> 5;
        int rb = gw >> 8;
        int kb = gw & 255;
        int r = l >> 2;
        int c = (l & 3) * 2;
        const float* base = x + (size_t)(rb * 16 + r) * IN_F + kb * 16 + c;
        float2 v0 = *(const float2*)(base);
        float2 v1 = *(const float2*)(base + 8 * IN_F);
        float2 v2 = *(const float2*)(base + 8);
        float2 v3 = *(const float2*)(base + 8 * IN_F + 8);
        __half2 h0 = __floats2half2_rn(v0.x, v0.y);
        __half2 h1 = __floats2half2_rn(v1.x, v1.y);
        __half2 h2 = __floats2half2_rn(v2.x, v2.y);
        __half2 h3 = __floats2half2_rn(v3.x, v3.y);
        uint4 o = make_uint4(*(uint32_t*)&h0, *(uint32_t*)&h1, *(uint32_t*)&h2, *(uint32_t*)&h3);
        *(uint4*)((char*)g_xh + (size_t)gw * 512 + l * 16) = o;

        float slo = v0.x + v0.y + v2.x + v2.y;     // row rb*16 + r
        float shi = v1.x + v1.y + v3.x + v3.y;     // row rb*16 + r + 8
        slo += __shfl_xor_sync(0xffffffffu, slo, 1);
        slo += __shfl_xor_sync(0xffffffffu, slo, 2);
        shi += __shfl_xor_sync(0xffffffffu, shi, 1);
        shi += __shfl_xor_sync(0xffffffffu, shi, 2);
        if ((l & 3) == 0) {
            atomicAdd(&g_rowsum[rb * 16 + r], slo);
            atomicAdd(&g_rowsum[rb * 16 + r + 8], shi);
        }
    } else {
        // ---- bias min/max ----
        int i0 = (b - WCONV_BLKS - XCVT_BLKS) * 512;
        int mn = 0x7fffffff, mx = (int)0x80000000;
        #pragma unroll
        for (int j = 0; j < 2; j++) {
            int v = bq[i0 + j * 256 + tid];
            mn = min(mn, v); mx = max(mx, v);
        }
        #pragma unroll
        for (int o = 16; o > 0; o >>= 1) {
            mn = min(mn, __shfl_xor_sync(0xffffffffu, mn, o));
            mx = max(mx, __shfl_xor_sync(0xffffffffu, mx, o));
        }
        if (l == 0) {
            atomicMin(&g_bmm[0], mn);
            atomicMax(&g_bmm[1], mx);
        }
    }
}

// ---------------- GEMM ----------------
// CTA tile: 128 (M) x 128 (N), BK=64, 4 warps (2x2 of 64x64), 3-stage cp.async,
// fragment-major SMEM, LDS.128 fragment loads, parity ping-pong register
// buffering, single barrier per step, 2 CTAs/SM. Scales computed inline.
#define BM      128
#define BN      128
#define BK      64
#define NSTAGE  3
#define NSTEPS  (IN_F / BK)          // 64
#define A_BYTES (8 * 4 * 512)        // 16384
#define B_BYTES (8 * 4 * 512)        // 16384
#define STG_B   (A_BYTES + B_BYTES)  // 32768
#define OFF_B   A_BYTES
#define SM_TOTAL (NSTAGE * STG_B)    // 98304
#define NTHR    128

__device__ __forceinline__ void issue_stage(char* smem, int stage, int tid,
                                            const char* abase, const char* bbase, int s) {
    uint32_t ubase = smem_u32(smem + stage * STG_B);
    #pragma unroll
    for (int j = 0; j < 8; j++) {
        int ch = j * 128 + tid;                  // 0..1023
        int mb   = ch >> 7;                      // local 16-row block 0..7
        int kb   = (ch >> 5) & 3;                // local k-block 0..3
        int lane = ch & 31;
        size_t goff = ((size_t)mb * KB_CNT + (size_t)(s * 4 + kb)) * 512 + lane * 16;
        CP_ASYNC16(ubase + ch * 16,         abase + goff);
        CP_ASYNC16(ubase + OFF_B + ch * 16, bbase + goff);
    }
}

__global__ void __launch_bounds__(NTHR, 2) k_gemm(
    const int* __restrict__ bias_q, float* __restrict__ out,
    const float* __restrict__ wmin, const float* __restrict__ wmax,
    const float* __restrict__ bmin, const float* __restrict__ bmax) {
    extern __shared__ char smem[];
    int tid = threadIdx.x;
    int wid = tid >> 5, lid = tid & 31;
    int n0 = blockIdx.x * BN;
    int m0 = blockIdx.y * BM;
    int wm = (wid >> 1) * 64;        // warp m offset (2 slots of 64)
    int wn = (wid & 1) * 64;         // warp n offset (2 slots of 64)

    // inline scale computation (constant per grid; cheap per CTA)
    float s_w = (*wmax - *wmin) / (float)(g_wmm[1] - g_wmm[0]);
    float off_w = *wmin - s_w * (float)g_wmm[0];
    float s_b = (*bmax - *bmin) / (float)(g_bmm[1] - g_bmm[0]);
    float off_b = *bmin - s_b * (float)g_bmm[0];

    const char* abase = (const char*)g_xh + (size_t)(m0 / 16) * KB_CNT * 512;
    const char* bbase = (const char*)g_wh + (size_t)(n0 / 16) * KB_CNT * 512;

    float acc[4][8][4];
    #pragma unroll
    for (int i = 0; i < 4; i++)
        #pragma unroll
        for (int j = 0; j < 8; j++)
            #pragma unroll
            for (int q = 0; q < 4; q++) acc[i][j][q] = 0.f;

    uint32_t sbase = smem_u32(smem);
    uint32_t lane16 = lid * 16;
    uint32_t aBlk[4], bBlk[4];
    #pragma unroll
    for (int f = 0; f < 4; f++) {
        aBlk[f] = ((wm >> 4) + f) * 4 * 512 + lane16;
        bBlk[f] = OFF_B + ((wn >> 4) + f) * 4 * 512 + lane16;
    }

    issue_stage(smem, 0, tid, abase, bbase, 0);
    CP_COMMIT();
    issue_stage(smem, 1, tid, abase, bbase, 1);
    CP_COMMIT();

    // parity ping-pong register buffers (no copies; kb loop fully unrolled)
    uint32_t aR[2][4][4], bR[2][4][4];

    for (int s = 0; s < NSTEPS; s++) {
        CP_WAIT(1);
        __syncthreads();
        // Single barrier per step: this barrier both (a) makes stage s's
        // cp.async data visible to all warps, and (b) guarantees all warps
        // finished reading stage s-1 (same ring buffer as s+2) last iteration.
        if (s + 2 < NSTEPS)
            issue_stage(smem, (s + 2) % NSTAGE, tid, abase, bbase, s + 2);
        CP_COMMIT();   // unconditional: keeps group arithmetic valid at the tail
        uint32_t stg = sbase + (s % NSTAGE) * STG_B;

        // prime kb=0 into parity buffer 0
        #pragma unroll
        for (int f = 0; f < 4; f++) {
            LDS128(aR[0][f][0], aR[0][f][1], aR[0][f][2], aR[0][f][3], stg + aBlk[f]);
            LDS128(bR[0][f][0], bR[0][f][1], bR[0][f][2], bR[0][f][3], stg + bBlk[f]);
        }
        #pragma unroll
        for (int kb = 0; kb < 4; kb++) {
            const int cur = kb & 1, nxt = cur ^ 1;
            if (kb < 3) {
                uint32_t koff = (kb + 1) * 512;
                #pragma unroll
                for (int f = 0; f < 4; f++) {
                    LDS128(aR[nxt][f][0], aR[nxt][f][1], aR[nxt][f][2], aR[nxt][f][3],
                           stg + aBlk[f] + koff);
                    LDS128(bR[nxt][f][0], bR[nxt][f][1], bR[nxt][f][2], bR[nxt][f][3],
                           stg + bBlk[f] + koff);
                }
            }
            #pragma unroll
            for (int mf = 0; mf < 4; mf++)
                #pragma unroll
                for (int g = 0; g < 4; g++) {
                    // B block g supplies n8 frags 2g (lo: q0,q2) and 2g+1 (hi: q1,q3)
                    mma16816(acc[mf][2*g][0], acc[mf][2*g][1], acc[mf][2*g][2], acc[mf][2*g][3],
                             aR[cur][mf][0], aR[cur][mf][1], aR[cur][mf][2], aR[cur][mf][3],
                             bR[cur][g][0], bR[cur][g][2]);
                    mma16816(acc[mf][2*g+1][0], acc[mf][2*g+1][1], acc[mf][2*g+1][2], acc[mf][2*g+1][3],
                             aR[cur][mf][0], aR[cur][mf][1], aR[cur][mf][2], aR[cur][mf][3],
                             bR[cur][g][1], bR[cur][g][3]);
                }
        }
    }

    // ---------------- epilogue: y = s_w*D + off_w*rowsum + bias_deq ----------------
    float rs0[4], rs1[4];
    #pragma unroll
    for (int mf = 0; mf < 4; mf++) {
        int r = m0 + wm + mf * 16 + (lid >> 2);
        rs0[mf] = off_w * g_rowsum[r];
        rs1[mf] = off_w * g_rowsum[r + 8];
    }
    float bv[8][2];
    #pragma unroll
    for (int nf = 0; nf < 8; nf++) {
        int c = n0 + wn + nf * 8 + (lid & 3) * 2;
        bv[nf][0] = fmaf(s_b, (float)bias_q[c], off_b);
        bv[nf][1] = fmaf(s_b, (float)bias_q[c + 1], off_b);
    }
    #pragma unroll
    for (int mf = 0; mf < 4; mf++) {
        int r0 = m0 + wm + mf * 16 + (lid >> 2);
        #pragma unroll
        for (int nf = 0; nf < 8; nf++) {
            int c = n0 + wn + nf * 8 + (lid & 3) * 2;
            float2 v0, v1;
            v0.x = fmaf(s_w, acc[mf][nf][0], rs0[mf] + bv[nf][0]);
            v0.y = fmaf(s_w, acc[mf][nf][1], rs0[mf] + bv[nf][1]);
            v1.x = fmaf(s_w, acc[mf][nf][2], rs1[mf] + bv[nf][0]);
            v1.y = fmaf(s_w, acc[mf][nf][3], rs1[mf] + bv[nf][1]);
            *(float2*)(out + (size_t)r0 * OUT_F + c)       = v0;
            *(float2*)(out + (size_t)(r0 + 8) * OUT_F + c) = v1;
        }
    }
}

// ---------------- launch ----------------
extern "C" void kernel_launch(void* const* d_in, const int* in_sizes, int n_in,
                              void* d_out, int out_size) {
    const float* x    = (const float*)d_in[0];
    const int*   wq   = (const int*)d_in[1];
    const int*   bq   = (const int*)d_in[2];
    const float* wmin = (const float*)d_in[3];
    const float* wmax = (const float*)d_in[4];
    const float* bmin = (const float*)d_in[5];
    const float* bmax = (const float*)d_in[6];
    float* out = (float*)d_out;

    k_init<<<(BATCH + 255) / 256, 256>>>();
    k_prep<<<WCONV_BLKS + XCVT_BLKS + 8, 256>>>(wq, x, bq);

    cudaFuncSetAttribute(k_gemm, cudaFuncAttributeMaxDynamicSharedMemorySize, SM_TOTAL);
    k_gemm<<<dim3(OUT_F / BN, BATCH / BM), NTHR, SM_TOTAL>>>(bq, out, wmin, wmax, bmin, bmax);
}